// round 13
// baseline (speedup 1.0000x reference)
#include <cuda_runtime.h>
#include <cuda_bf16.h>
#include <cstdint>

// Problem dims (fixed by the reference)
#define BATCH 4
#define SEQ   2048
#define DMODEL 1024
#define HEADS 16
#define DHEAD 64
#define ROWS  (BATCH * SEQ)   // 8192

// -------------------- scratch (device globals; no runtime alloc) ------------
__device__ float g_q[ROWS * DMODEL];
__device__ float g_k[ROWS * DMODEL];
__device__ float g_v[ROWS * DMODEL];
__device__ float g_attn[ROWS * DMODEL];

// -------------------- helpers ------------------------------------------------
__device__ __forceinline__ uint32_t f2tf32(float x) {
    uint32_t y;
    asm volatile("cvt.rna.tf32.f32 %0, %1;" : "=r"(y) : "f"(x));
    return y;
}

__device__ __forceinline__ float ex2(float x) {
    float y;
    asm volatile("ex2.approx.f32 %0, %1;" : "=f"(y) : "f"(x));
    return y;
}

__device__ __forceinline__ void mma_tf32(float c[4], const uint32_t a[4], const uint32_t b[2]) {
    asm volatile(
        "mma.sync.aligned.m16n8k8.row.col.f32.tf32.tf32.f32 "
        "{%0,%1,%2,%3}, {%4,%5,%6,%7}, {%8,%9}, {%0,%1,%2,%3};\n"
        : "+f"(c[0]), "+f"(c[1]), "+f"(c[2]), "+f"(c[3])
        : "r"(a[0]), "r"(a[1]), "r"(a[2]), "r"(a[3]),
          "r"(b[0]), "r"(b[1]));
}

// k-interleave within each 8-wide block: pos(k) = 8*(k>>3) + 2*(k&3) + ((k>>2)&1)
// This makes the fragment pair (k=tg, k=tg+4) adjacent -> one LDS.64.

// ============================================================================
// tf32 GEMM: C[M,N] = A[M,K] * B[K,N], row-major fp32.
// Block tile 128x128, K-tile 32, 256 threads (8 warps, 4x2 warp grid).
// Register-staged prefetch of the next K-tile hides LDG latency.
// A smem uses k-interleaved layout (stride 40) for LDS.64 A-fragments.
// ============================================================================
#define GBM 128
#define GBN 128
#define GBK 32
#define AS_STRIDE 40   // 32 + 8: banks 8*g distinct mod 32

__global__ void __launch_bounds__(256)
gemm_tf32_kernel(const float* __restrict__ A, const float* __restrict__ B,
                 float* __restrict__ C, int M, int N, int K) {
    __shared__ uint32_t As[GBM * AS_STRIDE];
    __shared__ uint32_t Bs[GBK][GBN + 8];

    const int tid  = threadIdx.x;
    const int wid  = tid >> 5;
    const int lane = tid & 31;
    const int g    = lane >> 2;
    const int tg   = lane & 3;
    const int wm   = (wid & 3) * 32;
    const int wn   = (wid >> 2) * 64;
    const int bm   = blockIdx.y * GBM;
    const int bn   = blockIdx.x * GBN;

    float acc[2][8][4];
    #pragma unroll
    for (int mi = 0; mi < 2; mi++)
        #pragma unroll
        for (int ni = 0; ni < 8; ni++)
            #pragma unroll
            for (int j = 0; j < 4; j++) acc[mi][ni][j] = 0.0f;

    float4 ra[4], rb[4];
    // initial prefetch (k0 = 0)
    #pragma unroll
    for (int i = 0; i < 4; i++) {
        int f = tid + i * 256;
        ra[i] = *(const float4*)(A + (size_t)(bm + (f >> 3)) * K + ((f & 7) << 2));
        rb[i] = *(const float4*)(B + (size_t)(f >> 5) * N + bn + ((f & 31) << 2));
    }

    for (int k0 = 0; k0 < K; k0 += GBK) {
        if (k0) __syncthreads();                 // prior tile fully consumed
        // ---- store staged tile to smem (tf32-round) ----
        #pragma unroll
        for (int i = 0; i < 4; i++) {
            int f  = tid + i * 256;
            int r  = f >> 3;
            int c4 = (f & 7) << 2;
            int base = r * AS_STRIDE + ((c4 >> 3) << 3) + ((c4 & 4) ? 1 : 0);
            As[base + 0] = f2tf32(ra[i].x);
            As[base + 2] = f2tf32(ra[i].y);
            As[base + 4] = f2tf32(ra[i].z);
            As[base + 6] = f2tf32(ra[i].w);
        }
        #pragma unroll
        for (int i = 0; i < 4; i++) {
            int f  = tid + i * 256;
            int r  = f >> 5;
            int c4 = (f & 31) << 2;
            Bs[r][c4 + 0] = f2tf32(rb[i].x);
            Bs[r][c4 + 1] = f2tf32(rb[i].y);
            Bs[r][c4 + 2] = f2tf32(rb[i].z);
            Bs[r][c4 + 3] = f2tf32(rb[i].w);
        }
        __syncthreads();

        // ---- prefetch next tile into registers (hidden by mma below) ----
        if (k0 + GBK < K) {
            #pragma unroll
            for (int i = 0; i < 4; i++) {
                int f = tid + i * 256;
                ra[i] = *(const float4*)(A + (size_t)(bm + (f >> 3)) * K + (k0 + GBK) + ((f & 7) << 2));
                rb[i] = *(const float4*)(B + (size_t)(k0 + GBK + (f >> 5)) * N + bn + ((f & 31) << 2));
            }
        }

        // ---- mma over smem ----
        #pragma unroll
        for (int kk = 0; kk < GBK; kk += 8) {
            uint32_t af[2][4];
            #pragma unroll
            for (int mi = 0; mi < 2; mi++) {
                int r = wm + mi * 16 + g;
                uint2 u0 = *(const uint2*)&As[r * AS_STRIDE + kk + 2 * tg];
                uint2 u1 = *(const uint2*)&As[(r + 8) * AS_STRIDE + kk + 2 * tg];
                af[mi][0] = u0.x; af[mi][2] = u0.y;
                af[mi][1] = u1.x; af[mi][3] = u1.y;
            }
            #pragma unroll
            for (int ni = 0; ni < 8; ni++) {
                uint32_t bf[2];
                bf[0] = Bs[kk + tg][wn + ni * 8 + g];
                bf[1] = Bs[kk + tg + 4][wn + ni * 8 + g];
                mma_tf32(acc[0][ni], af[0], bf);
                mma_tf32(acc[1][ni], af[1], bf);
            }
        }
    }

    // ---- epilogue ----
    #pragma unroll
    for (int mi = 0; mi < 2; mi++) {
        #pragma unroll
        for (int ni = 0; ni < 8; ni++) {
            int row = bm + wm + mi * 16 + g;
            int col = bn + wn + ni * 8 + 2 * tg;
            float2 v01 = make_float2(acc[mi][ni][0], acc[mi][ni][1]);
            float2 v23 = make_float2(acc[mi][ni][2], acc[mi][ni][3]);
            *(float2*)(C + (size_t)row * N + col)       = v01;
            *(float2*)(C + (size_t)(row + 8) * N + col) = v23;
        }
    }
}

// ============================================================================
// Flash attention v2 (tf32 mma):
//  - BQ=128 queries per block, 4 warps, 32 queries per warp (2 m-blocks)
//    -> each K/V fragment byte feeds 2x MMAs.
//  - k-interleaved smem layouts so every fragment load is one LDS.64.
//  - V stored transposed [d][key] with XOR swizzle (conflict-reduced both ways).
//    Swizzle constant is a function of the d-ROW: cx(d) = 2*((d>>2)&7).
//  - softmax via ex2 with log2e folded into the Q scale.
// Smem (dynamic, 108 KB): Qs[128][72], Ks[64][72], Vt[64][72], Ps[4][32][72]
// ============================================================================
#define BQ 128
#define FST 72   // common stride (72 mod 32 == 8 -> conflict-free frag loads)
#define FLASH_SMEM_WORDS (FST * (BQ + 64 + 64 + 4 * 32))
#define FLASH_SMEM_BYTES (FLASH_SMEM_WORDS * 4)

__global__ void __launch_bounds__(128)
flash_kernel(const float* __restrict__ Q, const float* __restrict__ Kb,
             const float* __restrict__ Vb, float* __restrict__ O) {
    extern __shared__ uint32_t sm[];
    uint32_t* Qs = sm;                       // 128 x 72 (k-interleaved)
    uint32_t* Ks = Qs + BQ * FST;            // 64 x 72  (k-interleaved)
    uint32_t* Vt = Ks + 64 * FST;            // 64 x 72  transposed [d][key], swizzled
    uint32_t* Ps = Vt + 64 * FST;            // 4 warps x 32 x 72 (k-interleaved)

    const int tid  = threadIdx.x;
    const int wid  = tid >> 5;
    const int lane = tid & 31;
    const int g    = lane >> 2;
    const int tg   = lane & 3;

    const int bh = blockIdx.y;
    const int b  = bh >> 4;
    const int hh = bh & 15;
    const int q0 = blockIdx.x * BQ;

    const float qscale = 0.125f * 1.44269504088896f;  // 1/sqrt(64) * log2(e)

    // positions of P columns 2tg, 2tg+1 inside an interleaved 8-block
    const int pa = ((2 * tg) & 3) * 2 + (tg >> 1);
    const int pb = (((2 * tg + 1) & 3) * 2) + (tg >> 1);

    // ---- fill Q tile (128 x 64), scaled, interleaved ----
    const float* qbase = Q + (size_t)(b * SEQ + q0) * DMODEL + hh * DHEAD;
    #pragma unroll
    for (int i = 0; i < 16; i++) {
        int f  = tid + i * 128;
        int r  = f >> 4;
        int c4 = (f & 15) << 2;
        float4 v = *(const float4*)(qbase + (size_t)r * DMODEL + c4);
        int base = r * FST + ((c4 >> 3) << 3) + ((c4 & 4) ? 1 : 0);
        Qs[base + 0] = f2tf32(v.x * qscale);
        Qs[base + 2] = f2tf32(v.y * qscale);
        Qs[base + 4] = f2tf32(v.z * qscale);
        Qs[base + 6] = f2tf32(v.w * qscale);
    }

    float o[2][8][4];
    #pragma unroll
    for (int mb = 0; mb < 2; mb++)
        #pragma unroll
        for (int di = 0; di < 8; di++)
            #pragma unroll
            for (int j = 0; j < 4; j++) o[mb][di][j] = 0.0f;
    float m0[2] = {-1e30f, -1e30f}, m1[2] = {-1e30f, -1e30f};
    float l0[2] = {0.0f, 0.0f},    l1[2] = {0.0f, 0.0f};

    const float* kbase = Kb + (size_t)b * SEQ * DMODEL + hh * DHEAD;
    const float* vbase = Vb + (size_t)b * SEQ * DMODEL + hh * DHEAD;
    uint32_t* Pw = Ps + wid * 32 * FST;
    const int rw = wid * 32;                 // warp's query-row base in tile

    for (int n0 = 0; n0 < SEQ; n0 += 64) {
        __syncthreads();                     // prior tile fully consumed
        // ---- fill K (interleaved) and V (transposed + swizzled) ----
        #pragma unroll
        for (int i = 0; i < 8; i++) {
            int f  = tid + i * 128;
            int r  = f >> 4;
            int c4 = (f & 15) << 2;
            float4 kv = *(const float4*)(kbase + (size_t)(n0 + r) * DMODEL + c4);
            int kb = r * FST + ((c4 >> 3) << 3) + ((c4 & 4) ? 1 : 0);
            Ks[kb + 0] = f2tf32(kv.x);
            Ks[kb + 2] = f2tf32(kv.y);
            Ks[kb + 4] = f2tf32(kv.z);
            Ks[kb + 6] = f2tf32(kv.w);
            float4 vv = *(const float4*)(vbase + (size_t)(n0 + r) * DMODEL + c4);
            int posr = ((r >> 3) << 3) + ((r & 3) << 1) + ((r >> 2) & 1);
            int cx   = (c4 >> 1) & 14;       // 2*((d>>2)&7); same for d=c4..c4+3
            int vb0  = c4 * FST + (posr ^ cx);
            Vt[vb0]           = f2tf32(vv.x);
            Vt[vb0 + FST]     = f2tf32(vv.y);
            Vt[vb0 + 2 * FST] = f2tf32(vv.z);
            Vt[vb0 + 3 * FST] = f2tf32(vv.w);
        }
        __syncthreads();

        // ---- S = (Q*scale') K^T : 32 rows x 64 keys per warp ----
        float s[2][8][4];
        #pragma unroll
        for (int mb = 0; mb < 2; mb++)
            #pragma unroll
            for (int ni = 0; ni < 8; ni++)
                #pragma unroll
                for (int j = 0; j < 4; j++) s[mb][ni][j] = 0.0f;

        #pragma unroll
        for (int kk = 0; kk < 8; kk++) {
            uint32_t af[2][4];
            #pragma unroll
            for (int mb = 0; mb < 2; mb++) {
                int row = rw + mb * 16 + g;
                uint2 u0 = *(const uint2*)&Qs[row * FST + kk * 8 + 2 * tg];
                uint2 u1 = *(const uint2*)&Qs[(row + 8) * FST + kk * 8 + 2 * tg];
                af[mb][0] = u0.x; af[mb][2] = u0.y;
                af[mb][1] = u1.x; af[mb][3] = u1.y;
            }
            #pragma unroll
            for (int ni = 0; ni < 8; ni++) {
                uint2 bu = *(const uint2*)&Ks[(ni * 8 + g) * FST + kk * 8 + 2 * tg];
                uint32_t bf[2] = {bu.x, bu.y};
                mma_tf32(s[0][ni], af[0], bf);
                mma_tf32(s[1][ni], af[1], bf);
            }
        }

        // ---- online softmax (log2 domain), P stored interleaved ----
        #pragma unroll
        for (int mb = 0; mb < 2; mb++) {
            float t0 = -1e30f, t1 = -1e30f;
            #pragma unroll
            for (int ni = 0; ni < 8; ni++) {
                t0 = fmaxf(t0, fmaxf(s[mb][ni][0], s[mb][ni][1]));
                t1 = fmaxf(t1, fmaxf(s[mb][ni][2], s[mb][ni][3]));
            }
            t0 = fmaxf(t0, __shfl_xor_sync(0xffffffffu, t0, 1));
            t0 = fmaxf(t0, __shfl_xor_sync(0xffffffffu, t0, 2));
            t1 = fmaxf(t1, __shfl_xor_sync(0xffffffffu, t1, 1));
            t1 = fmaxf(t1, __shfl_xor_sync(0xffffffffu, t1, 2));

            float mn0 = fmaxf(m0[mb], t0);
            float mn1 = fmaxf(m1[mb], t1);
            float a0 = ex2(m0[mb] - mn0);
            float a1 = ex2(m1[mb] - mn1);

            float rs0 = 0.0f, rs1 = 0.0f;
            #pragma unroll
            for (int ni = 0; ni < 8; ni++) {
                float p0 = ex2(s[mb][ni][0] - mn0);
                float p1 = ex2(s[mb][ni][1] - mn0);
                float p2 = ex2(s[mb][ni][2] - mn1);
                float p3 = ex2(s[mb][ni][3] - mn1);
                rs0 += p0 + p1;
                rs1 += p2 + p3;
                int pr0 = (mb * 16 + g) * FST + ni * 8;
                int pr1 = pr0 + 8 * FST;
                Pw[pr0 + pa] = f2tf32(p0);
                Pw[pr0 + pb] = f2tf32(p1);
                Pw[pr1 + pa] = f2tf32(p2);
                Pw[pr1 + pb] = f2tf32(p3);
            }
            rs0 += __shfl_xor_sync(0xffffffffu, rs0, 1);
            rs0 += __shfl_xor_sync(0xffffffffu, rs0, 2);
            rs1 += __shfl_xor_sync(0xffffffffu, rs1, 1);
            rs1 += __shfl_xor_sync(0xffffffffu, rs1, 2);

            m0[mb] = mn0; m1[mb] = mn1;
            l0[mb] = l0[mb] * a0 + rs0;
            l1[mb] = l1[mb] * a1 + rs1;

            #pragma unroll
            for (int di = 0; di < 8; di++) {
                o[mb][di][0] *= a0;
                o[mb][di][1] *= a0;
                o[mb][di][2] *= a1;
                o[mb][di][3] *= a1;
            }
        }
        __syncwarp();    // order P stores before P fragment loads (cross-lane)

        // ---- O += P V ----
        #pragma unroll
        for (int kk = 0; kk < 8; kk++) {
            uint32_t af[2][4];
            #pragma unroll
            for (int mb = 0; mb < 2; mb++) {
                int row = mb * 16 + g;
                uint2 u0 = *(const uint2*)&Pw[row * FST + kk * 8 + 2 * tg];
                uint2 u1 = *(const uint2*)&Pw[(row + 8) * FST + kk * 8 + 2 * tg];
                af[mb][0] = u0.x; af[mb][2] = u0.y;
                af[mb][1] = u1.x; af[mb][3] = u1.y;
            }
            #pragma unroll
            for (int di = 0; di < 8; di++) {
                // FIX (R8 bug): load swizzle must match the store swizzle of
                // row d = di*8 + g, i.e. cx(d) = 2*((d>>2)&7) = (4*di + 2*(g>>2)) & 14.
                // R8 omitted the 2*(g>>2) term -> lanes with g>=4 read wrong V.
                int cxx = (4 * di + 2 * (g >> 2)) & 14;
                uint2 bu = *(const uint2*)&Vt[(di * 8 + g) * FST + ((kk * 8 + 2 * tg) ^ cxx)];
                uint32_t bf[2] = {bu.x, bu.y};
                mma_tf32(o[0][di], af[0], bf);
                mma_tf32(o[1][di], af[1], bf);
            }
        }
    }

    // ---- normalize and write ----
    #pragma unroll
    for (int mb = 0; mb < 2; mb++) {
        float i0 = 1.0f / l0[mb];
        float i1 = 1.0f / l1[mb];
        int row0 = q0 + rw + mb * 16 + g;
        int row1 = row0 + 8;
        #pragma unroll
        for (int di = 0; di < 8; di++) {
            int col = hh * DHEAD + di * 8 + 2 * tg;
            float2 v01 = make_float2(o[mb][di][0] * i0, o[mb][di][1] * i0);
            float2 v23 = make_float2(o[mb][di][2] * i1, o[mb][di][3] * i1);
            *(float2*)(O + (size_t)(b * SEQ + row0) * DMODEL + col) = v01;
            *(float2*)(O + (size_t)(b * SEQ + row1) * DMODEL + col) = v23;
        }
    }
}

// ============================================================================
// kernel_launch
// ============================================================================
extern "C" void kernel_launch(void* const* d_in, const int* in_sizes, int n_in,
                              void* d_out, int out_size) {
    (void)in_sizes; (void)n_in; (void)out_size;
    const float* x  = (const float*)d_in[0];
    const float* Wq = (const float*)d_in[1];
    const float* Wk = (const float*)d_in[2];
    const float* Wv = (const float*)d_in[3];
    const float* Wo = (const float*)d_in[4];
    float* out = (float*)d_out;

    float *q, *k, *v, *attn;
    cudaGetSymbolAddress((void**)&q,    g_q);
    cudaGetSymbolAddress((void**)&k,    g_k);
    cudaGetSymbolAddress((void**)&v,    g_v);
    cudaGetSymbolAddress((void**)&attn, g_attn);

    dim3 ggrid(DMODEL / GBN, ROWS / GBM);   // (8, 64)

    gemm_tf32_kernel<<<ggrid, 256>>>(x, Wq, q, ROWS, DMODEL, DMODEL);
    gemm_tf32_kernel<<<ggrid, 256>>>(x, Wk, k, ROWS, DMODEL, DMODEL);
    gemm_tf32_kernel<<<ggrid, 256>>>(x, Wv, v, ROWS, DMODEL, DMODEL);

    cudaFuncSetAttribute(flash_kernel,
                         cudaFuncAttributeMaxDynamicSharedMemorySize,
                         FLASH_SMEM_BYTES);
    flash_kernel<<<dim3(SEQ / BQ, BATCH * HEADS), 128, FLASH_SMEM_BYTES>>>(q, k, v, attn);

    gemm_tf32_kernel<<<ggrid, 256>>>(attn, Wo, out, ROWS, DMODEL, DMODEL);
}

// round 16
// speedup vs baseline: 1.1696x; 1.1696x over previous
#include <cuda_runtime.h>
#include <cuda_bf16.h>
#include <cstdint>

// Problem dims (fixed by the reference)
#define BATCH 4
#define SEQ   2048
#define DMODEL 1024
#define HEADS 16
#define DHEAD 64
#define ROWS  (BATCH * SEQ)   // 8192

// -------------------- scratch (device globals; no runtime alloc) ------------
__device__ float g_q[ROWS * DMODEL];
__device__ float g_k[ROWS * DMODEL];
__device__ float g_v[ROWS * DMODEL];
__device__ float g_attn[ROWS * DMODEL];

// -------------------- helpers ------------------------------------------------
__device__ __forceinline__ uint32_t f2tf32(float x) {
    uint32_t y;
    asm volatile("cvt.rna.tf32.f32 %0, %1;" : "=r"(y) : "f"(x));
    return y;
}

__device__ __forceinline__ float ex2(float x) {
    float y;
    asm volatile("ex2.approx.f32 %0, %1;" : "=f"(y) : "f"(x));
    return y;
}

__device__ __forceinline__ void mma_tf32(float c[4], const uint32_t a[4], const uint32_t b[2]) {
    asm volatile(
        "mma.sync.aligned.m16n8k8.row.col.f32.tf32.tf32.f32 "
        "{%0,%1,%2,%3}, {%4,%5,%6,%7}, {%8,%9}, {%0,%1,%2,%3};\n"
        : "+f"(c[0]), "+f"(c[1]), "+f"(c[2]), "+f"(c[3])
        : "r"(a[0]), "r"(a[1]), "r"(a[2]), "r"(a[3]),
          "r"(b[0]), "r"(b[1]));
}

// k-interleave within each 8-wide block: pos(k) = 8*(k>>3) + 2*(k&3) + ((k>>2)&1)
// Makes the fragment pair (k=tg, k=tg+4) adjacent -> one LDS.64.

// ============================================================================
// tf32 GEMM (R7 version, known-good 136us): C[M,N] = A[M,K] * B[K,N].
// Block tile 128x128, K-tile 32, 256 threads (8 warps, 4x2 warp grid).
// Single-buffered smem, tf32-round at fill.
// ============================================================================
#define GBM 128
#define GBN 128
#define GBK 32

__global__ void __launch_bounds__(256)
gemm_tf32_kernel(const float* __restrict__ A, const float* __restrict__ B,
                 float* __restrict__ C, int M, int N, int K) {
    __shared__ uint32_t As[GBM][GBK + 4];    // stride 36
    __shared__ uint32_t Bs[GBK][GBN + 8];    // stride 136

    const int tid  = threadIdx.x;
    const int wid  = tid >> 5;
    const int lane = tid & 31;
    const int g    = lane >> 2;
    const int tg   = lane & 3;
    const int wm   = (wid & 3) * 32;
    const int wn   = (wid >> 2) * 64;
    const int bm   = blockIdx.y * GBM;
    const int bn   = blockIdx.x * GBN;

    float acc[2][8][4];
    #pragma unroll
    for (int mi = 0; mi < 2; mi++)
        #pragma unroll
        for (int ni = 0; ni < 8; ni++)
            #pragma unroll
            for (int j = 0; j < 4; j++) acc[mi][ni][j] = 0.0f;

    for (int k0 = 0; k0 < K; k0 += GBK) {
        #pragma unroll
        for (int i = 0; i < 4; i++) {
            int f  = tid + i * 256;
            int r  = f >> 3;
            int c4 = (f & 7) << 2;
            float4 v = *(const float4*)(A + (size_t)(bm + r) * K + k0 + c4);
            As[r][c4 + 0] = f2tf32(v.x);
            As[r][c4 + 1] = f2tf32(v.y);
            As[r][c4 + 2] = f2tf32(v.z);
            As[r][c4 + 3] = f2tf32(v.w);
        }
        #pragma unroll
        for (int i = 0; i < 4; i++) {
            int f  = tid + i * 256;
            int r  = f >> 5;
            int c4 = (f & 31) << 2;
            float4 v = *(const float4*)(B + (size_t)(k0 + r) * N + bn + c4);
            Bs[r][c4 + 0] = f2tf32(v.x);
            Bs[r][c4 + 1] = f2tf32(v.y);
            Bs[r][c4 + 2] = f2tf32(v.z);
            Bs[r][c4 + 3] = f2tf32(v.w);
        }
        __syncthreads();

        #pragma unroll
        for (int kk = 0; kk < GBK; kk += 8) {
            uint32_t af[2][4];
            #pragma unroll
            for (int mi = 0; mi < 2; mi++) {
                int r = wm + mi * 16;
                af[mi][0] = As[r + g][kk + tg];
                af[mi][1] = As[r + g + 8][kk + tg];
                af[mi][2] = As[r + g][kk + tg + 4];
                af[mi][3] = As[r + g + 8][kk + tg + 4];
            }
            #pragma unroll
            for (int ni = 0; ni < 8; ni++) {
                uint32_t bf[2];
                bf[0] = Bs[kk + tg][wn + ni * 8 + g];
                bf[1] = Bs[kk + tg + 4][wn + ni * 8 + g];
                mma_tf32(acc[0][ni], af[0], bf);
                mma_tf32(acc[1][ni], af[1], bf);
            }
        }
        __syncthreads();
    }

    #pragma unroll
    for (int mi = 0; mi < 2; mi++) {
        #pragma unroll
        for (int ni = 0; ni < 8; ni++) {
            int row = bm + wm + mi * 16 + g;
            int col = bn + wn + ni * 8 + 2 * tg;
            float2 v01 = make_float2(acc[mi][ni][0], acc[mi][ni][1]);
            float2 v23 = make_float2(acc[mi][ni][2], acc[mi][ni][3]);
            *(float2*)(C + (size_t)row * N + col)       = v01;
            *(float2*)(C + (size_t)(row + 8) * N + col) = v23;
        }
    }
}

// ============================================================================
// Flash attention v3 (tf32 mma):
//  - BQ=128 queries per block, 8 warps x 16 rows each (256 threads)
//    -> regs <= 128 -> 2 CTAs/SM -> 16 warps/SM (4/SMSP).
//  - K/V fill amortized over 128 queries (half of R7's fill traffic).
//  - k-interleaved smem layouts: every fragment load is one LDS.64 (from R13).
//  - V transposed [d][key] with XOR swizzle; corrected load swizzle
//    cx(d) = 2*((d>>2)&7) = (4*di + 2*(g>>2)) & 14 (validated in R13).
//  - ex2 softmax with log2e folded into the Q scale (validated in R13).
// Smem (dynamic, 110.6 KB): Qs[128][72], Ks[64][72], Vt[64][72], Ps[8][16][72]
// ============================================================================
#define BQ 128
#define FST 72
#define FLASH_SMEM_WORDS (FST * (BQ + 64 + 64 + 8 * 16))
#define FLASH_SMEM_BYTES (FLASH_SMEM_WORDS * 4)

__global__ void __launch_bounds__(256, 2)
flash_kernel(const float* __restrict__ Q, const float* __restrict__ Kb,
             const float* __restrict__ Vb, float* __restrict__ O) {
    extern __shared__ uint32_t sm[];
    uint32_t* Qs = sm;                       // 128 x 72 (k-interleaved)
    uint32_t* Ks = Qs + BQ * FST;            // 64 x 72  (k-interleaved)
    uint32_t* Vt = Ks + 64 * FST;            // 64 x 72  transposed [d][key], swizzled
    uint32_t* Ps = Vt + 64 * FST;            // 8 warps x 16 x 72 (k-interleaved)

    const int tid  = threadIdx.x;
    const int wid  = tid >> 5;
    const int lane = tid & 31;
    const int g    = lane >> 2;
    const int tg   = lane & 3;

    const int bh = blockIdx.y;
    const int b  = bh >> 4;
    const int hh = bh & 15;
    const int q0 = blockIdx.x * BQ;

    const float qscale = 0.125f * 1.44269504088896f;  // 1/sqrt(64) * log2(e)

    // positions of P columns 2tg, 2tg+1 inside an interleaved 8-block
    const int pa = ((2 * tg) & 3) * 2 + (tg >> 1);
    const int pb = (((2 * tg + 1) & 3) * 2) + (tg >> 1);

    // ---- fill Q tile (128 x 64), scaled, interleaved ----
    const float* qbase = Q + (size_t)(b * SEQ + q0) * DMODEL + hh * DHEAD;
    #pragma unroll
    for (int i = 0; i < 8; i++) {
        int f  = tid + i * 256;
        int r  = f >> 4;
        int c4 = (f & 15) << 2;
        float4 v = *(const float4*)(qbase + (size_t)r * DMODEL + c4);
        int base = r * FST + ((c4 >> 3) << 3) + ((c4 & 4) ? 1 : 0);
        Qs[base + 0] = f2tf32(v.x * qscale);
        Qs[base + 2] = f2tf32(v.y * qscale);
        Qs[base + 4] = f2tf32(v.z * qscale);
        Qs[base + 6] = f2tf32(v.w * qscale);
    }
    __syncthreads();

    // ---- preload Q A-fragments for all 8 k-steps (held in regs) ----
    const int rw = wid * 16;                 // warp's query-row base in tile
    uint32_t qa[8][4];
    {
        int row = rw + g;
        #pragma unroll
        for (int kk = 0; kk < 8; kk++) {
            uint2 u0 = *(const uint2*)&Qs[row * FST + kk * 8 + 2 * tg];
            uint2 u1 = *(const uint2*)&Qs[(row + 8) * FST + kk * 8 + 2 * tg];
            qa[kk][0] = u0.x; qa[kk][2] = u0.y;
            qa[kk][1] = u1.x; qa[kk][3] = u1.y;
        }
    }

    float o[8][4];
    #pragma unroll
    for (int di = 0; di < 8; di++)
        #pragma unroll
        for (int j = 0; j < 4; j++) o[di][j] = 0.0f;
    float m0 = -1e30f, m1 = -1e30f;
    float l0 = 0.0f,  l1 = 0.0f;

    const float* kbase = Kb + (size_t)b * SEQ * DMODEL + hh * DHEAD;
    const float* vbase = Vb + (size_t)b * SEQ * DMODEL + hh * DHEAD;
    uint32_t* Pw = Ps + wid * 16 * FST;

    for (int n0 = 0; n0 < SEQ; n0 += 64) {
        __syncthreads();                     // prior tile fully consumed
        // ---- fill K (interleaved) and V (transposed + swizzled) ----
        #pragma unroll
        for (int i = 0; i < 4; i++) {
            int f  = tid + i * 256;
            int r  = f >> 4;
            int c4 = (f & 15) << 2;
            float4 kv = *(const float4*)(kbase + (size_t)(n0 + r) * DMODEL + c4);
            int kb = r * FST + ((c4 >> 3) << 3) + ((c4 & 4) ? 1 : 0);
            Ks[kb + 0] = f2tf32(kv.x);
            Ks[kb + 2] = f2tf32(kv.y);
            Ks[kb + 4] = f2tf32(kv.z);
            Ks[kb + 6] = f2tf32(kv.w);
            float4 vv = *(const float4*)(vbase + (size_t)(n0 + r) * DMODEL + c4);
            int posr = ((r >> 3) << 3) + ((r & 3) << 1) + ((r >> 2) & 1);
            int cx   = (c4 >> 1) & 14;       // 2*((d>>2)&7); same for d=c4..c4+3
            int vb0  = c4 * FST + (posr ^ cx);
            Vt[vb0]           = f2tf32(vv.x);
            Vt[vb0 + FST]     = f2tf32(vv.y);
            Vt[vb0 + 2 * FST] = f2tf32(vv.z);
            Vt[vb0 + 3 * FST] = f2tf32(vv.w);
        }
        __syncthreads();

        // ---- S = (Q*scale') K^T : 16 rows x 64 keys per warp ----
        float s[8][4];
        #pragma unroll
        for (int ni = 0; ni < 8; ni++)
            #pragma unroll
            for (int j = 0; j < 4; j++) s[ni][j] = 0.0f;

        #pragma unroll
        for (int kk = 0; kk < 8; kk++) {
            #pragma unroll
            for (int ni = 0; ni < 8; ni++) {
                uint2 bu = *(const uint2*)&Ks[(ni * 8 + g) * FST + kk * 8 + 2 * tg];
                uint32_t bf[2] = {bu.x, bu.y};
                mma_tf32(s[ni], qa[kk], bf);
            }
        }

        // ---- online softmax (log2 domain), P stored interleaved ----
        float t0 = -1e30f, t1 = -1e30f;
        #pragma unroll
        for (int ni = 0; ni < 8; ni++) {
            t0 = fmaxf(t0, fmaxf(s[ni][0], s[ni][1]));
            t1 = fmaxf(t1, fmaxf(s[ni][2], s[ni][3]));
        }
        t0 = fmaxf(t0, __shfl_xor_sync(0xffffffffu, t0, 1));
        t0 = fmaxf(t0, __shfl_xor_sync(0xffffffffu, t0, 2));
        t1 = fmaxf(t1, __shfl_xor_sync(0xffffffffu, t1, 1));
        t1 = fmaxf(t1, __shfl_xor_sync(0xffffffffu, t1, 2));

        float mn0 = fmaxf(m0, t0);
        float mn1 = fmaxf(m1, t1);
        float a0 = ex2(m0 - mn0);
        float a1 = ex2(m1 - mn1);

        float rs0 = 0.0f, rs1 = 0.0f;
        #pragma unroll
        for (int ni = 0; ni < 8; ni++) {
            float p0 = ex2(s[ni][0] - mn0);
            float p1 = ex2(s[ni][1] - mn0);
            float p2 = ex2(s[ni][2] - mn1);
            float p3 = ex2(s[ni][3] - mn1);
            rs0 += p0 + p1;
            rs1 += p2 + p3;
            int pr0 = g * FST + ni * 8;
            int pr1 = pr0 + 8 * FST;
            Pw[pr0 + pa] = f2tf32(p0);
            Pw[pr0 + pb] = f2tf32(p1);
            Pw[pr1 + pa] = f2tf32(p2);
            Pw[pr1 + pb] = f2tf32(p3);
        }
        rs0 += __shfl_xor_sync(0xffffffffu, rs0, 1);
        rs0 += __shfl_xor_sync(0xffffffffu, rs0, 2);
        rs1 += __shfl_xor_sync(0xffffffffu, rs1, 1);
        rs1 += __shfl_xor_sync(0xffffffffu, rs1, 2);

        m0 = mn0; m1 = mn1;
        l0 = l0 * a0 + rs0;
        l1 = l1 * a1 + rs1;

        #pragma unroll
        for (int di = 0; di < 8; di++) {
            o[di][0] *= a0;
            o[di][1] *= a0;
            o[di][2] *= a1;
            o[di][3] *= a1;
        }
        __syncwarp();    // order P stores before P fragment loads (cross-lane)

        // ---- O += P V ----
        #pragma unroll
        for (int kk = 0; kk < 8; kk++) {
            uint32_t af[4];
            {
                uint2 u0 = *(const uint2*)&Pw[g * FST + kk * 8 + 2 * tg];
                uint2 u1 = *(const uint2*)&Pw[(g + 8) * FST + kk * 8 + 2 * tg];
                af[0] = u0.x; af[2] = u0.y;
                af[1] = u1.x; af[3] = u1.y;
            }
            #pragma unroll
            for (int di = 0; di < 8; di++) {
                int cxx = (4 * di + 2 * (g >> 2)) & 14;   // matches store swizzle of d=di*8+g
                uint2 bu = *(const uint2*)&Vt[(di * 8 + g) * FST + ((kk * 8 + 2 * tg) ^ cxx)];
                uint32_t bf[2] = {bu.x, bu.y};
                mma_tf32(o[di], af, bf);
            }
        }
    }

    // ---- normalize and write ----
    float i0 = 1.0f / l0;
    float i1 = 1.0f / l1;
    int row0 = q0 + rw + g;
    int row1 = row0 + 8;
    #pragma unroll
    for (int di = 0; di < 8; di++) {
        int col = hh * DHEAD + di * 8 + 2 * tg;
        float2 v01 = make_float2(o[di][0] * i0, o[di][1] * i0);
        float2 v23 = make_float2(o[di][2] * i1, o[di][3] * i1);
        *(float2*)(O + (size_t)(b * SEQ + row0) * DMODEL + col) = v01;
        *(float2*)(O + (size_t)(b * SEQ + row1) * DMODEL + col) = v23;
    }
}

// ============================================================================
// kernel_launch
// ============================================================================
extern "C" void kernel_launch(void* const* d_in, const int* in_sizes, int n_in,
                              void* d_out, int out_size) {
    (void)in_sizes; (void)n_in; (void)out_size;
    const float* x  = (const float*)d_in[0];
    const float* Wq = (const float*)d_in[1];
    const float* Wk = (const float*)d_in[2];
    const float* Wv = (const float*)d_in[3];
    const float* Wo = (const float*)d_in[4];
    float* out = (float*)d_out;

    float *q, *k, *v, *attn;
    cudaGetSymbolAddress((void**)&q,    g_q);
    cudaGetSymbolAddress((void**)&k,    g_k);
    cudaGetSymbolAddress((void**)&v,    g_v);
    cudaGetSymbolAddress((void**)&attn, g_attn);

    dim3 ggrid(DMODEL / GBN, ROWS / GBM);   // (8, 64)

    gemm_tf32_kernel<<<ggrid, 256>>>(x, Wq, q, ROWS, DMODEL, DMODEL);
    gemm_tf32_kernel<<<ggrid, 256>>>(x, Wk, k, ROWS, DMODEL, DMODEL);
    gemm_tf32_kernel<<<ggrid, 256>>>(x, Wv, v, ROWS, DMODEL, DMODEL);

    cudaFuncSetAttribute(flash_kernel,
                         cudaFuncAttributeMaxDynamicSharedMemorySize,
                         FLASH_SMEM_BYTES);
    flash_kernel<<<dim3(SEQ / BQ, BATCH * HEADS), 256, FLASH_SMEM_BYTES>>>(q, k, v, attn);

    gemm_tf32_kernel<<<ggrid, 256>>>(attn, Wo, out, ROWS, DMODEL, DMODEL);
}